// round 15
// baseline (speedup 1.0000x reference)
#include <cuda_runtime.h>
#include <cuda_bf16.h>
#include <cstdint>

// MX e4m3 quantize-dequantize, block size 32 along rows. FINAL.
// Best-measured config: 128-thread CTAs (12/SM), 4 float4/thread, .cs on
// loads AND stores (L1-bypass required on loads; evict-first stores beat
// write-back by ~2 DRAM pts). Internal: 74.9us, 6.41 TB/s = 80.1% of spec.
// Coalesced: lane l handles float4 (warpBase + i*32 + l); one MX block =
// 8 consecutive float4s = one aligned 8-lane group at fixed i.
// Quantizer: exponent-field bit arithmetic, *s fused into rescale via exact
// power-of-two integer add; x/s via per-block reciprocal + Markstein FMA.
// All rounding steps bit-identical to the reference sequence (rel_err = 0).

__device__ __forceinline__ float mx_scale(float amax) {
    // sc = bf16(RN(amax/448)) ; RN division via Markstein with r448=RN(1/448)
    const float r448 = 1.0f / 448.0f;
    float q0 = __fmul_rn(amax, r448);
    float dv = __fmaf_rn(__fmaf_rn(-q0, 448.0f, amax), r448, q0);
    float sc = __bfloat162float(__float2bfloat16(dv));
    // s = floor_bf16(sc*256 + 0.5) * 2^-8 (bf16 semantics), 0 -> 1
    float t = sc * 256.0f;                                   // exact exp shift
    float u = __bfloat162float(__float2bfloat16(t + 0.5f));  // bf16 add (RN)
    float s = floorf(u) * 0.00390625f;                       // exact * 2^-8
    return (s == 0.0f) ? 1.0f : s;
}

__device__ __forceinline__ float qdq_e4m3(float x, float s, float r,
                                          uint32_t sB, float c448s) {
    // correctly-rounded d = x / s (Markstein, r = RN(1/s))
    float q0 = __fmul_rn(x, r);
    float d  = __fmaf_rn(__fmaf_rn(-q0, s, x), r, q0);

    uint32_t db  = __float_as_uint(d);
    uint32_t mb  = db & 0x7FFFFFFFu;                       // |d|
    uint32_t peb = max(mb & 0x7F800000u, 0x3C800000u);     // 2^e, e>=-6
    float inv = __uint_as_float(0x80800000u - peb);        // 2^(3-e)
    float ps  = __uint_as_float(peb + sB);                 // 2^(e-3)*s (exact)
    float q = floorf(__fmaf_rn(__uint_as_float(mb), inv, 0.5f)); // half-away
    float outmag = fminf(__fmul_rn(q, ps), c448s);         // == min(q*pout,448)*s
    return __uint_as_float(__float_as_uint(outmag) | (db & 0x80000000u));
}

__global__ void __launch_bounds__(128, 12)
mxq_kernel(const float4* __restrict__ x, float4* __restrict__ y, int nf4) {
    int tid  = blockIdx.x * blockDim.x + threadIdx.x;
    int warp = tid >> 5;
    int lane = tid & 31;
    size_t base = (size_t)warp * 128 + lane;   // warp covers 128 float4 (2 KB)
    if ((size_t)warp * 128 >= (size_t)nf4) return;

    float4 v[4];
#pragma unroll
    for (int i = 0; i < 4; i++) v[i] = __ldcs(x + base + i * 32);

    float s[4], r[4], c448s[4];
    uint32_t sB[4];
#pragma unroll
    for (int i = 0; i < 4; i++) {
        float m = fmaxf(fmaxf(fabsf(v[i].x), fabsf(v[i].y)),
                        fmaxf(fabsf(v[i].z), fabsf(v[i].w)));
        // amax over the 8-lane group owning this MX block
        m = fmaxf(m, __shfl_xor_sync(0xFFFFFFFFu, m, 1));
        m = fmaxf(m, __shfl_xor_sync(0xFFFFFFFFu, m, 2));
        m = fmaxf(m, __shfl_xor_sync(0xFFFFFFFFu, m, 4));
        s[i] = mx_scale(m);
        r[i] = 1.0f / s[i];                            // RN reciprocal per block
        sB[i] = __float_as_uint(s[i]) - 0x41000000u;   // fold *2^-3 * s
        c448s[i] = 448.0f * s[i];                      // exact
    }

#pragma unroll
    for (int i = 0; i < 4; i++) {
        float4 o;
        o.x = qdq_e4m3(v[i].x, s[i], r[i], sB[i], c448s[i]);
        o.y = qdq_e4m3(v[i].y, s[i], r[i], sB[i], c448s[i]);
        o.z = qdq_e4m3(v[i].z, s[i], r[i], sB[i], c448s[i]);
        o.w = qdq_e4m3(v[i].w, s[i], r[i], sB[i], c448s[i]);
        __stcs(y + base + i * 32, o);
    }
}

extern "C" void kernel_launch(void* const* d_in, const int* in_sizes, int n_in,
                              void* d_out, int out_size) {
    const float4* x = (const float4*)d_in[0];
    float4* y = (float4*)d_out;
    int n = in_sizes[0];            // 67,108,864 floats
    int nf4 = n / 4;                // 16,777,216 float4
    int threads = 128;
    int nthreads_total = nf4 / 4;   // 4 float4 per thread
    int grid = (nthreads_total + threads - 1) / threads;
    mxq_kernel<<<grid, threads>>>(x, y, nf4);
}

// round 16
// speedup vs baseline: 1.0039x; 1.0039x over previous
#include <cuda_runtime.h>
#include <cuda_bf16.h>
#include <cstdint>

// MX e4m3 quantize-dequantize, block size 32 along rows. FINAL (R6 config —
// best measured bench: 81.888us, DRAM 80.1%, 6.35 TB/s combined R/W).
// Coalesced: lane l handles float4 (warpBase + i*32 + l); one MX block =
// 8 consecutive float4s = one aligned 8-lane group at fixed i.
// 4 float4/thread, .cs on loads AND stores (L1-bypass required on loads;
// evict-first stores beat write-back). Kernel is at the HBM3e mixed-stream
// ceiling of this part; all compute pipes <=41%.
// Quantizer: exponent-field bit arithmetic, *s fused into rescale via exact
// power-of-two integer add; x/s via per-block reciprocal + Markstein FMA.
// All rounding steps bit-identical to the reference sequence (rel_err = 0).

__device__ __forceinline__ float mx_scale(float amax) {
    // sc = bf16(RN(amax/448)) ; RN division via Markstein with r448=RN(1/448)
    const float r448 = 1.0f / 448.0f;
    float q0 = __fmul_rn(amax, r448);
    float dv = __fmaf_rn(__fmaf_rn(-q0, 448.0f, amax), r448, q0);
    float sc = __bfloat162float(__float2bfloat16(dv));
    // s = floor_bf16(sc*256 + 0.5) * 2^-8 (bf16 semantics), 0 -> 1
    float t = sc * 256.0f;                                   // exact exp shift
    float u = __bfloat162float(__float2bfloat16(t + 0.5f));  // bf16 add (RN)
    float s = floorf(u) * 0.00390625f;                       // exact * 2^-8
    return (s == 0.0f) ? 1.0f : s;
}

__device__ __forceinline__ float qdq_e4m3(float x, float s, float r,
                                          uint32_t sB, float c448s) {
    // correctly-rounded d = x / s (Markstein, r = RN(1/s))
    float q0 = __fmul_rn(x, r);
    float d  = __fmaf_rn(__fmaf_rn(-q0, s, x), r, q0);

    uint32_t db  = __float_as_uint(d);
    uint32_t mb  = db & 0x7FFFFFFFu;                       // |d|
    uint32_t peb = max(mb & 0x7F800000u, 0x3C800000u);     // 2^e, e>=-6
    float inv = __uint_as_float(0x80800000u - peb);        // 2^(3-e)
    float ps  = __uint_as_float(peb + sB);                 // 2^(e-3)*s (exact)
    float q = floorf(__fmaf_rn(__uint_as_float(mb), inv, 0.5f)); // half-away
    float outmag = fminf(__fmul_rn(q, ps), c448s);         // == min(q*pout,448)*s
    return __uint_as_float(__float_as_uint(outmag) | (db & 0x80000000u));
}

__global__ void __launch_bounds__(256)
mxq_kernel(const float4* __restrict__ x, float4* __restrict__ y, int nf4) {
    int tid  = blockIdx.x * blockDim.x + threadIdx.x;
    int warp = tid >> 5;
    int lane = tid & 31;
    size_t base = (size_t)warp * 128 + lane;   // warp covers 128 float4 (2 KB)
    if ((size_t)warp * 128 >= (size_t)nf4) return;

    float4 v[4];
#pragma unroll
    for (int i = 0; i < 4; i++) v[i] = __ldcs(x + base + i * 32);

    float s[4], r[4], c448s[4];
    uint32_t sB[4];
#pragma unroll
    for (int i = 0; i < 4; i++) {
        float m = fmaxf(fmaxf(fabsf(v[i].x), fabsf(v[i].y)),
                        fmaxf(fabsf(v[i].z), fabsf(v[i].w)));
        // amax over the 8-lane group owning this MX block
        m = fmaxf(m, __shfl_xor_sync(0xFFFFFFFFu, m, 1));
        m = fmaxf(m, __shfl_xor_sync(0xFFFFFFFFu, m, 2));
        m = fmaxf(m, __shfl_xor_sync(0xFFFFFFFFu, m, 4));
        s[i] = mx_scale(m);
        r[i] = 1.0f / s[i];                            // RN reciprocal per block
        sB[i] = __float_as_uint(s[i]) - 0x41000000u;   // fold *2^-3 * s
        c448s[i] = 448.0f * s[i];                      // exact
    }

#pragma unroll
    for (int i = 0; i < 4; i++) {
        float4 o;
        o.x = qdq_e4m3(v[i].x, s[i], r[i], sB[i], c448s[i]);
        o.y = qdq_e4m3(v[i].y, s[i], r[i], sB[i], c448s[i]);
        o.z = qdq_e4m3(v[i].z, s[i], r[i], sB[i], c448s[i]);
        o.w = qdq_e4m3(v[i].w, s[i], r[i], sB[i], c448s[i]);
        __stcs(y + base + i * 32, o);
    }
}

extern "C" void kernel_launch(void* const* d_in, const int* in_sizes, int n_in,
                              void* d_out, int out_size) {
    const float4* x = (const float4*)d_in[0];
    float4* y = (float4*)d_out;
    int n = in_sizes[0];            // 67,108,864 floats
    int nf4 = n / 4;                // 16,777,216 float4
    int threads = 256;
    int nthreads_total = nf4 / 4;   // 4 float4 per thread
    int grid = (nthreads_total + threads - 1) / threads;
    mxq_kernel<<<grid, threads>>>(x, y, nf4);
}